// round 13
// baseline (speedup 1.0000x reference)
#include <cuda_runtime.h>
#include <math.h>
#include <stdint.h>

#define NB   64
#define NT   128
#define NIN  300
#define ND   64
#define NC   10
#define BETAC 0.8f

typedef unsigned long long u64;

// ---------------- scratch (device globals; no allocations) ----------------
static __device__ float g_W[(size_t)NT*ND*ND];      // W_s = Uh^s, s=1..128 at (s-1)*4096
static __device__ float g_M[(size_t)NT*ND*ND];      // M_t = W_{t+1}^T Ux
static __device__ float g_A[(size_t)NT*ND*ND];      // A_t = M_t W_{t+1}
static __device__ float g_P[(size_t)NT*ND*NC];      // P_t = W_{t+1}^T Wd
static __device__ float g_u1r[NB*NT*ND];
static __device__ float g_u1i[NB*NT*ND];
static __device__ float g_L1r[(size_t)NT*NB*ND*ND]; // tilde-frame layer outputs
static __device__ float g_L1i[(size_t)NT*NB*ND*ND];
static __device__ float g_ux2r[(size_t)NT*NB*ND*ND];
static __device__ float g_ux2i[(size_t)NT*NB*ND*ND];

__device__ __forceinline__ float sigmoidf_(float v) { return 1.0f / (1.0f + expf(-v)); }

// ---- packed f32x2 helpers (sm_103a) ----
__device__ __forceinline__ u64 pk2(float a) {
    u64 r; asm("mov.b64 %0, {%1, %1};" : "=l"(r) : "f"(a)); return r;
}
__device__ __forceinline__ void fma2(u64 &d, u64 a, u64 b) {
    asm("fma.rn.f32x2 %0, %1, %2, %0;" : "+l"(d) : "l"(a), "l"(b));
}
union UF { ulonglong2 u; float4 f; };
#define GETC(v,kk) ((kk)==0?(v).x:((kk)==1?(v).y:((kk)==2?(v).z:(v).w)))

// ---- cluster / DSMEM helpers ----
__device__ __forceinline__ uint32_t smem_u32_(const void* p) {
    uint32_t a;
    asm("{ .reg .u64 t; cvta.to.shared.u64 t, %1; cvt.u32.u64 %0, t; }" : "=r"(a) : "l"(p));
    return a;
}
__device__ __forceinline__ uint32_t mapa_(uint32_t a, uint32_t rank) {
    uint32_t r; asm("mapa.shared::cluster.u32 %0, %1, %2;" : "=r"(r) : "r"(a), "r"(rank));
    return r;
}
__device__ __forceinline__ void stsc16(uint32_t a, float4 v) {
    asm volatile("st.shared::cluster.v4.b32 [%0], {%1,%2,%3,%4};"
        :: "r"(a), "r"(__float_as_uint(v.x)), "r"(__float_as_uint(v.y)),
           "r"(__float_as_uint(v.z)), "r"(__float_as_uint(v.w)) : "memory");
}
__device__ __forceinline__ uint32_t ctarank_() {
    uint32_t r; asm("mov.u32 %0, %%cluster_ctarank;" : "=r"(r)); return r;
}
#define CLUSTER_ARRIVE() asm volatile("barrier.cluster.arrive.aligned;" ::: "memory")
#define CLUSTER_WAIT()   asm volatile("barrier.cluster.wait.aligned;"   ::: "memory")
#define CLUSTER_SYNC() do { CLUSTER_ARRIVE(); CLUSTER_WAIT(); } while(0)

// ---------------- precompute: W powers by doubling ----------------
__global__ void copy_w1(const float* __restrict__ Uh) {
    g_W[blockIdx.x*256 + threadIdx.x] = Uh[blockIdx.x*256 + threadIdx.x];
}

// W_{base+j} = W_base @ W_j, j = blockIdx.x+1
__global__ void __launch_bounds__(256) pow_level(int base) {
    __shared__ float sA[4096], sB[4096];
    const int j = blockIdx.x + 1;
    const float* A = g_W + (size_t)(base-1)*4096;
    const float* B = g_W + (size_t)(j-1)*4096;
    float* C = g_W + (size_t)(base+j-1)*4096;
    const int tid = threadIdx.x;
    for (int i = tid; i < 4096; i += 256) { sA[i] = A[i]; sB[i] = B[i]; }
    __syncthreads();
    const int tx = tid & 15, ty = tid >> 4;
    const int i0 = ty*4, j0 = tx*4;
    float acc[4][4] = {};
    for (int k = 0; k < 64; k++) {
#pragma unroll
        for (int r = 0; r < 4; r++) {
            float a = sA[(i0+r)*64 + k];
#pragma unroll
            for (int c = 0; c < 4; c++) acc[r][c] = fmaf(a, sB[k*64 + j0 + c], acc[r][c]);
        }
    }
#pragma unroll
    for (int r = 0; r < 4; r++)
#pragma unroll
        for (int c = 0; c < 4; c++) C[(i0+r)*64 + j0 + c] = acc[r][c];
}

// per t: M_t = W^T Ux ; A_t = M_t W ; P_t = W^T Wd   (W = W_{t+1})
__global__ void __launch_bounds__(256) maps_kernel(const float* __restrict__ Ux,
                                                   const float* __restrict__ Wd) {
    extern __shared__ float dsm[];
    float* sWT = dsm;          // sWT[i*64+k] = W[k][i]
    float* sU  = dsm + 4096;
    float* sM  = dsm + 8192;
    float* sWd = dsm + 12288;  // 640
    const int t = blockIdx.x;
    const float* W = g_W + (size_t)t*4096;
    const int tid = threadIdx.x;
    for (int idx = tid; idx < 4096; idx += 256) {
        sWT[(idx & 63)*64 + (idx >> 6)] = W[idx];
        sU[idx] = Ux[idx];
    }
    for (int idx = tid; idx < 640; idx += 256) sWd[idx] = Wd[idx];
    __syncthreads();
    const int tx = tid & 15, ty = tid >> 4;
    const int i0 = ty*4, j0 = tx*4;
    float acc[4][4] = {};
    for (int k = 0; k < 64; k++) {
#pragma unroll
        for (int r = 0; r < 4; r++) {
            float a = sWT[(i0+r)*64 + k];
#pragma unroll
            for (int c = 0; c < 4; c++) acc[r][c] = fmaf(a, sU[k*64 + j0 + c], acc[r][c]);
        }
    }
#pragma unroll
    for (int r = 0; r < 4; r++)
#pragma unroll
        for (int c = 0; c < 4; c++) {
            sM[(i0+r)*64 + j0 + c] = acc[r][c];
            g_M[(size_t)t*4096 + (i0+r)*64 + j0 + c] = acc[r][c];
        }
    __syncthreads();
    float acc2[4][4] = {};
    for (int k = 0; k < 64; k++) {
#pragma unroll
        for (int r = 0; r < 4; r++) {
            float a = sM[(i0+r)*64 + k];
#pragma unroll
            for (int c = 0; c < 4; c++)  // W[k][j] = sWT[j*64+k]
                acc2[r][c] = fmaf(a, sWT[(j0+c)*64 + k], acc2[r][c]);
        }
    }
#pragma unroll
    for (int r = 0; r < 4; r++)
#pragma unroll
        for (int c = 0; c < 4; c++)
            g_A[(size_t)t*4096 + (i0+r)*64 + j0 + c] = acc2[r][c];
    // P = W^T Wd  [64][10]
    for (int idx = tid; idx < 640; idx += 256) {
        int i = idx / 10, jj = idx % 10;
        float s = 0.f;
        for (int k = 0; k < 64; k++) s = fmaf(sWT[i*64 + k], sWd[k*10 + jj], s);
        g_P[(size_t)t*640 + idx] = s;
    }
}

// ---------------- K1: projections + tilde-frame rank-1 vectors -------------
__global__ void proj_kernel(const float* __restrict__ x,
                            const float* __restrict__ amp_w,
                            const float* __restrict__ amp_b,
                            const float* __restrict__ phase_w,
                            const float* __restrict__ phase_b)
{
    __shared__ float xsh[NIN];
    __shared__ float red[ND];
    __shared__ float ssr[ND], ssi[ND];
    __shared__ float sMT[ND*65];
    const int blk = blockIdx.x;      // b*NT + t
    const int t   = blk & (NT-1);
    const int tid = threadIdx.x;
    const float* xrow = x + (size_t)blk * NIN;
    const float* Mt = g_M + (size_t)t*4096;

    for (int i = tid; i < NIN; i += ND) xsh[i] = xrow[i];
    for (int i = tid; i < ND*ND; i += ND) sMT[(i & 63)*65 + (i >> 6)] = Mt[i];
    __syncthreads();

    float a = amp_b[tid], p = phase_b[tid];
#pragma unroll 4
    for (int k = 0; k < NIN; k++) {
        float xv = xsh[k];
        a = fmaf(xv, amp_w[k*ND + tid], a);
        p = fmaf(xv, phase_w[k*ND + tid], p);
    }
    red[tid] = a * a;
    __syncthreads();
    if (tid == 0) {
        float s = 0.f;
        for (int i = 0; i < ND; i++) s += red[i];
        red[0] = 1.0f / sqrtf(s);
    }
    __syncthreads();
    float amp = a * red[0];
    ssr[tid] = amp * cosf(p);
    ssi[tid] = amp * sinf(p);
    __syncthreads();

    float ur = 0.f, ui = 0.f;
#pragma unroll 4
    for (int e = 0; e < ND; e++) {
        float u = sMT[e*65 + tid];     // M_t[tid][e]
        ur = fmaf(u, ssr[e], ur);
        ui = fmaf(u, ssi[e], ui);
    }
    g_u1r[(size_t)blk*ND + tid] = ur;
    g_u1i[(size_t)blk*ND + tid] = ui;
}

// ---------------- K2/K4: tilde-frame clustered scan -------------------------
// Per step: N = lam*X + oml*H (elementwise, full, local), trace = Frobenius
// (local, deterministic), C = N@N (complex; my 32 rows), H' = b*C/tr+(1-b)*N.
// ONE 16KB H exchange + ONE cluster barrier per step; H double-buffered.
#define S_HR0 0
#define S_HI0 4096
#define S_HR1 8192
#define S_HI1 12288
#define S_NR  16384
#define S_NI  20480
#define SCAN2_FLOATS 24576

template<int MODE>
__global__ void __launch_bounds__(256, 1) __cluster_dims__(2, 1, 1)
scan2_kernel(const float* __restrict__ lam_ptr)
{
    extern __shared__ float sm[];
    __shared__ float suvr[ND], suvi[ND];
    __shared__ float red[8];

    const uint32_t rank  = ctarank_();
    const uint32_t prank = rank ^ 1u;
    const int b    = blockIdx.x >> 1;
    const int row0 = (int)rank * 32;
    const int tid  = threadIdx.x;
    const int tx = tid & 15, ty = tid >> 4;    // ty 0..15
    const int j0 = tx * 4;
    const int e0 = ty * 4;                     // full-matrix rows (N phase)
    const int g0 = row0 + ty * 2;              // my output rows (2 per thread)
    const float lam = sigmoidf_(lam_ptr[0]);
    const float oml = 1.0f - lam;
    const float ob  = 1.0f - BETAC;
    float* sNr = sm + S_NR;
    float* sNi = sm + S_NI;

    for (int i = tid; i < 4096; i += 256) {
        sm[S_HR0 + i] = ((i >> 6) == (i & 63)) ? (1.0f/ND) : 0.0f;
        sm[S_HI0 + i] = 0.0f;
    }
    __syncthreads();
    const uint32_t myBase = smem_u32_(sm);
    const uint32_t pBase  = mapa_(myBase, prank);

    CLUSTER_ARRIVE();   // pairs with step-0 WAIT

    for (int t = 0; t < NT; t++) {
        const int p = t & 1;
        float* sHr = sm + (p ? S_HR1 : S_HR0);   // read buffer
        float* sHi = sm + (p ? S_HI1 : S_HI0);
        float* dHr = sm + (p ? S_HR0 : S_HR1);   // write buffer
        float* dHi = sm + (p ? S_HI0 : S_HI1);
        const uint32_t pdHr = pBase + (uint32_t)(p ? S_HR0 : S_HR1) * 4u;
        const uint32_t pdHi = pBase + (uint32_t)(p ? S_HI0 : S_HI1) * 4u;

        // prefetch X for my full-matrix rows
        float4 xr4[4], xi4[4];
        if (MODE == 1) {
            const size_t base = ((size_t)t*NB + b)*4096;
#pragma unroll
            for (int rr = 0; rr < 4; rr++) {
                xr4[rr] = *(const float4*)&g_ux2r[base + (size_t)(e0+rr)*64 + j0];
                xi4[rr] = *(const float4*)&g_ux2i[base + (size_t)(e0+rr)*64 + j0];
            }
        } else {
            if (tid < ND) {
                suvr[tid] = g_u1r[((size_t)b*NT + t)*ND + tid];
                suvi[tid] = g_u1i[((size_t)b*NT + t)*ND + tid];
            }
        }

        CLUSTER_WAIT();                 // peer H rows (prev step) have arrived
        if (MODE == 0) __syncthreads(); // suv visible

        // ---- N = lam*X + oml*H (full matrix, local) + Frobenius partial ----
        float sq = 0.f;
        float4 vrj, vij; float vre[4], vie[4];
        if (MODE == 0) {
            vrj = *(const float4*)&suvr[j0];
            vij = *(const float4*)&suvi[j0];
#pragma unroll
            for (int rr = 0; rr < 4; rr++) { vre[rr] = suvr[e0+rr]; vie[rr] = suvi[e0+rr]; }
        }
#pragma unroll
        for (int rr = 0; rr < 4; rr++) {
            const int e = e0 + rr;
            float4 hr = *(const float4*)&sHr[e*64 + j0];
            float4 hi = *(const float4*)&sHi[e*64 + j0];
            float4 nr, ni;
            if (MODE == 0) {
                nr.x = fmaf(oml, hr.x, lam*(vre[rr]*vrj.x + vie[rr]*vij.x));
                nr.y = fmaf(oml, hr.y, lam*(vre[rr]*vrj.y + vie[rr]*vij.y));
                nr.z = fmaf(oml, hr.z, lam*(vre[rr]*vrj.z + vie[rr]*vij.z));
                nr.w = fmaf(oml, hr.w, lam*(vre[rr]*vrj.w + vie[rr]*vij.w));
                ni.x = fmaf(oml, hi.x, lam*(vie[rr]*vrj.x - vre[rr]*vij.x));
                ni.y = fmaf(oml, hi.y, lam*(vie[rr]*vrj.y - vre[rr]*vij.y));
                ni.z = fmaf(oml, hi.z, lam*(vie[rr]*vrj.z - vre[rr]*vij.z));
                ni.w = fmaf(oml, hi.w, lam*(vie[rr]*vrj.w - vre[rr]*vij.w));
            } else {
                nr.x = fmaf(oml, hr.x, xr4[rr].x);
                nr.y = fmaf(oml, hr.y, xr4[rr].y);
                nr.z = fmaf(oml, hr.z, xr4[rr].z);
                nr.w = fmaf(oml, hr.w, xr4[rr].w);
                ni.x = fmaf(oml, hi.x, xi4[rr].x);
                ni.y = fmaf(oml, hi.y, xi4[rr].y);
                ni.z = fmaf(oml, hi.z, xi4[rr].z);
                ni.w = fmaf(oml, hi.w, xi4[rr].w);
            }
            *(float4*)&sNr[e*64 + j0] = nr;
            *(float4*)&sNi[e*64 + j0] = ni;
            sq = fmaf(nr.x, nr.x, sq); sq = fmaf(nr.y, nr.y, sq);
            sq = fmaf(nr.z, nr.z, sq); sq = fmaf(nr.w, nr.w, sq);
            sq = fmaf(ni.x, ni.x, sq); sq = fmaf(ni.y, ni.y, sq);
            sq = fmaf(ni.z, ni.z, sq); sq = fmaf(ni.w, ni.w, sq);
        }
        // deterministic reduce: warp tree -> red[8] -> fixed-order sum
#pragma unroll
        for (int o = 16; o > 0; o >>= 1)
            sq += __shfl_down_sync(0xffffffffu, sq, o);
        if ((tid & 31) == 0) red[tid >> 5] = sq;
        __syncthreads();   // sN + red visible
        const float tr = ((((((red[0]+red[1])+red[2])+red[3])+red[4])+red[5])+red[6])+red[7];

        // ---- C[myrows,:] = N[myrows,:] @ N (complex square) ----
        UF cR[2], cI[2];
#pragma unroll
        for (int r = 0; r < 2; r++) { cR[r].f = make_float4(0,0,0,0); cI[r].f = make_float4(0,0,0,0); }
#pragma unroll 2
        for (int k0 = 0; k0 < 64; k0 += 4) {
            float4 ar4[2], ai4[2];
#pragma unroll
            for (int r = 0; r < 2; r++) {
                ar4[r] = *(const float4*)&sNr[(g0+r)*64 + k0];
                ai4[r] = *(const float4*)&sNi[(g0+r)*64 + k0];
            }
#pragma unroll
            for (int kk = 0; kk < 4; kk++) {
                const int k = k0 + kk;
                UF br, bi;
                br.f = *(const float4*)&sNr[k*64 + j0];
                bi.f = *(const float4*)&sNi[k*64 + j0];
#pragma unroll
                for (int r = 0; r < 2; r++) {
                    float av  = GETC(ar4[r], kk);
                    float avi = GETC(ai4[r], kk);
                    u64 arp = pk2(av);
                    u64 aip = pk2(avi);
                    u64 ain = pk2(-avi);
                    fma2(cR[r].u.x, arp, br.u.x); fma2(cR[r].u.y, arp, br.u.y);
                    fma2(cR[r].u.x, ain, bi.u.x); fma2(cR[r].u.y, ain, bi.u.y);
                    fma2(cI[r].u.x, arp, bi.u.x); fma2(cI[r].u.y, arp, bi.u.y);
                    fma2(cI[r].u.x, aip, br.u.x); fma2(cI[r].u.y, aip, br.u.y);
                }
            }
        }

        // ---- epilogue: H' = b*C/tr + (1-b)*N ; local + peer + gmem ----
        const float sc = BETAC / tr;
        float* gr = g_L1r + ((size_t)t*NB + b)*4096;
        float* gi = g_L1i + ((size_t)t*NB + b)*4096;
#pragma unroll
        for (int rr = 0; rr < 2; rr++) {
            const int g = g0 + rr;
            float4 nr = *(const float4*)&sNr[g*64 + j0];
            float4 ni = *(const float4*)&sNi[g*64 + j0];
            float4 hR, hI;
            hR.x = fmaf(sc, cR[rr].f.x, ob*nr.x);  hR.y = fmaf(sc, cR[rr].f.y, ob*nr.y);
            hR.z = fmaf(sc, cR[rr].f.z, ob*nr.z);  hR.w = fmaf(sc, cR[rr].f.w, ob*nr.w);
            hI.x = fmaf(sc, cI[rr].f.x, ob*ni.x);  hI.y = fmaf(sc, cI[rr].f.y, ob*ni.y);
            hI.z = fmaf(sc, cI[rr].f.z, ob*ni.z);  hI.w = fmaf(sc, cI[rr].f.w, ob*ni.w);
            *(float4*)&dHr[g*64 + j0] = hR;
            *(float4*)&dHi[g*64 + j0] = hI;
            stsc16(pdHr + (uint32_t)(g*64 + j0)*4u, hR);
            stsc16(pdHi + (uint32_t)(g*64 + j0)*4u, hI);
            *(float4*)&gr[g*64 + j0] = hR;
            *(float4*)&gi[g*64 + j0] = hI;
        }
        __syncthreads();   // local H writes visible CTA-wide
        CLUSTER_ARRIVE();  // release H stores to peer
    }

    CLUSTER_WAIT();
    CLUSTER_SYNC();        // no exit while peer DSMEM stores in flight
}

// ---------------- K3: layer-2 x-side conjugation (tilde frame, A_t) --------
__global__ void __launch_bounds__(256) uxconj_kernel(const float* __restrict__ lam_ptr)
{
    extern __shared__ float sm[];
    float* sUx  = sm;
    float* sUxT = sm + 4096;
    float* sXr  = sm + 8192;
    float* sXi  = sm + 12288;
    float* sTr  = sm + 16384;
    float* sTi  = sm + 20480;
    const int tid = threadIdx.x;
    const int tx = tid & 15, ty = tid >> 4;
    const int i0 = ty * 4;
    const float lam = sigmoidf_(lam_ptr[0]);
    const size_t base = (size_t)blockIdx.x * 4096;
    const float* At = g_A + (size_t)(blockIdx.x >> 6) * 4096;   // blk = t*NB+b

    for (int i = tid; i < ND*ND; i += 256) {
        float v = At[i];
        sUx[i] = v;
        sUxT[(i & 63)*64 + (i >> 6)] = v;
        sXr[i] = g_L1r[base + i];
        sXi[i] = g_L1i[base + i];
    }
    __syncthreads();

    {
        UF aR[4], aI[4];
#pragma unroll
        for (int r = 0; r < 4; r++) { aR[r].f = make_float4(0,0,0,0); aI[r].f = make_float4(0,0,0,0); }
        const ulonglong2* xr2 = (const ulonglong2*)sXr;
        const ulonglong2* xi2 = (const ulonglong2*)sXi;
#pragma unroll 2
        for (int k0 = 0; k0 < ND; k0 += 4) {
            float4 a4[4];
#pragma unroll
            for (int r = 0; r < 4; r++) a4[r] = *(const float4*)&sUx[(i0+r)*64 + k0];
#pragma unroll
            for (int kk = 0; kk < 4; kk++) {
                ulonglong2 br = xr2[(k0+kk)*16 + tx];
                ulonglong2 bi = xi2[(k0+kk)*16 + tx];
#pragma unroll
                for (int r = 0; r < 4; r++) {
                    u64 ap = pk2(GETC(a4[r], kk));
                    fma2(aR[r].u.x, ap, br.x); fma2(aR[r].u.y, ap, br.y);
                    fma2(aI[r].u.x, ap, bi.x); fma2(aI[r].u.y, ap, bi.y);
                }
            }
        }
#pragma unroll
        for (int r = 0; r < 4; r++) {
            ((float4*)sTr)[(i0+r)*16 + tx] = aR[r].f;
            ((float4*)sTi)[(i0+r)*16 + tx] = aI[r].f;
        }
    }
    __syncthreads();

    {
        UF oR[4], oI[4];
#pragma unroll
        for (int r = 0; r < 4; r++) { oR[r].f = make_float4(0,0,0,0); oI[r].f = make_float4(0,0,0,0); }
        const ulonglong2* uxT2 = (const ulonglong2*)sUxT;
#pragma unroll 2
        for (int k0 = 0; k0 < ND; k0 += 4) {
            float4 ar4[4], ai4[4];
#pragma unroll
            for (int r = 0; r < 4; r++) {
                ar4[r] = *(const float4*)&sTr[(i0+r)*64 + k0];
                ai4[r] = *(const float4*)&sTi[(i0+r)*64 + k0];
            }
#pragma unroll
            for (int kk = 0; kk < 4; kk++) {
                ulonglong2 b4 = uxT2[(k0+kk)*16 + tx];
#pragma unroll
                for (int r = 0; r < 4; r++) {
                    u64 arp = pk2(GETC(ar4[r], kk));
                    u64 aip = pk2(GETC(ai4[r], kk));
                    fma2(oR[r].u.x, arp, b4.x); fma2(oR[r].u.y, arp, b4.y);
                    fma2(oI[r].u.x, aip, b4.x); fma2(oI[r].u.y, aip, b4.y);
                }
            }
        }
        float4* gr = (float4*)(g_ux2r + base);
        float4* gi = (float4*)(g_ux2i + base);
#pragma unroll
        for (int r = 0; r < 4; r++) {
            float4 vR = oR[r].f, vI = oI[r].f;
            vR.x *= lam; vR.y *= lam; vR.z *= lam; vR.w *= lam;
            vI.x *= lam; vI.y *= lam; vI.z *= lam; vI.w *= lam;
            gr[(i0+r)*16 + tx] = vR;
            gi[(i0+r)*16 + tx] = vI;
        }
    }
}

// ---------------- K5: dense + measurement + log (tilde frame, P_t) ---------
__global__ void __launch_bounds__(256) dense_meas_kernel(const float* __restrict__ dlam_ptr,
                                                         const float* __restrict__ mk,
                                                         float* __restrict__ out)
{
    __shared__ float sRr[ND*ND], sRi[ND*ND];
    __shared__ float sW[ND*NC];
    __shared__ float tmpr[ND*NC], tmpi[ND*NC];
    __shared__ float sgr[NC*NC], sgi[NC*NC];
    __shared__ float svr[NC*NC], svi[NC*NC];
    const int blk = blockIdx.x;     // t*NB + b
    const int tid = threadIdx.x;
    const size_t base = (size_t)blk * 4096;
    const float* Pt = g_P + (size_t)(blk >> 6) * 640;

    for (int i = tid; i < ND*ND; i += 256) { sRr[i] = g_L1r[base + i]; sRi[i] = g_L1i[base + i]; }
    for (int i = tid; i < ND*NC; i += 256) sW[i] = Pt[i];
    if (tid < NC) {
        float nrm = 0.f;
        for (int c = 0; c < NC; c++) {
            float vr = mk[(tid*NC + c)*2 + 0];
            float vi = mk[(tid*NC + c)*2 + 1];
            nrm += vr*vr + vi*vi;
        }
        float inv = 1.0f / sqrtf(nrm);
        for (int c = 0; c < NC; c++) {
            svr[tid*NC + c] = mk[(tid*NC + c)*2 + 0] * inv;
            svi[tid*NC + c] = mk[(tid*NC + c)*2 + 1] * inv;
        }
    }
    __syncthreads();

    for (int idx = tid; idx < ND*NC; idx += 256) {
        int d = idx / NC, c = idx % NC;
        float ar = 0.f, ai = 0.f;
#pragma unroll 4
        for (int e = 0; e < ND; e++) {
            float w = sW[e*NC + c];
            ar = fmaf(sRr[d*64 + e], w, ar);
            ai = fmaf(sRi[d*64 + e], w, ai);
        }
        tmpr[idx] = ar; tmpi[idx] = ai;
    }
    __syncthreads();

    if (tid < NC*NC) {
        int c = tid / NC, f = tid % NC;
        float ar = 0.f, ai = 0.f;
#pragma unroll 4
        for (int d = 0; d < ND; d++) {
            float w = sW[d*NC + c];
            ar = fmaf(w, tmpr[d*NC + f], ar);
            ai = fmaf(w, tmpi[d*NC + f], ai);
        }
        float dlam = sigmoidf_(dlam_ptr[0]);
        ar = dlam * ar + ((c == f) ? (1.0f - dlam) / NC : 0.0f);
        ai = dlam * ai;
        sgr[tid] = ar; sgi[tid] = ai;
    }
    __syncthreads();

    if (tid < NC) {
        float tr = 0.f;
        for (int c = 0; c < NC; c++) tr += sgr[c*NC + c];
        float invtr = 1.0f / tr;
        int k = tid;
        float p = 0.f;
        for (int c = 0; c < NC; c++) {
            float vrc = svr[k*NC + c], vic = svi[k*NC + c];
            for (int d = 0; d < NC; d++) {
                float vrd = svr[k*NC + d], vid = svi[k*NC + d];
                p += (vrc*vrd + vic*vid) * sgr[c*NC + d]
                   + (vic*vrd - vrc*vid) * sgi[c*NC + d];
            }
        }
        p *= invtr;
        int t = blk / NB, b = blk % NB;
        out[((size_t)b*NT + t)*NC + k] = logf(p);
    }
}

// ---------------- launch ----------------
extern "C" void kernel_launch(void* const* d_in, const int* in_sizes, int n_in,
                              void* d_out, int out_size)
{
    const float* x        = (const float*)d_in[0];
    const float* amp_w    = (const float*)d_in[1];
    const float* amp_b    = (const float*)d_in[2];
    const float* phase_w  = (const float*)d_in[3];
    const float* phase_b  = (const float*)d_in[4];
    const float* Ux       = (const float*)d_in[5];
    const float* Uh       = (const float*)d_in[6];
    const float* cell_l   = (const float*)d_in[7];
    const float* dense_w  = (const float*)d_in[8];
    const float* dense_l  = (const float*)d_in[9];
    const float* meas     = (const float*)d_in[10];
    float* out = (float*)d_out;

    const int SCAN_SMEM = SCAN2_FLOATS * 4;      // 96 KB
    const int UX_SMEM   = 6 * 4096 * 4;          // 96 KB
    const int MAPS_SMEM = (3*4096 + 640) * 4;    // ~51.7 KB
    cudaFuncSetAttribute(scan2_kernel<0>, cudaFuncAttributeMaxDynamicSharedMemorySize, SCAN_SMEM);
    cudaFuncSetAttribute(scan2_kernel<1>, cudaFuncAttributeMaxDynamicSharedMemorySize, SCAN_SMEM);
    cudaFuncSetAttribute(uxconj_kernel,   cudaFuncAttributeMaxDynamicSharedMemorySize, UX_SMEM);
    cudaFuncSetAttribute(maps_kernel,     cudaFuncAttributeMaxDynamicSharedMemorySize, MAPS_SMEM);

    // precompute W powers (doubling), then per-t maps
    copy_w1<<<16, 256>>>(Uh);
    for (int l = 0; l < 7; l++) {
        int base = 1 << l;
        int cnt  = (128 - base < base) ? (128 - base) : base;
        pow_level<<<cnt, 256>>>(base);
    }
    maps_kernel<<<NT, 256, MAPS_SMEM>>>(Ux, dense_w);

    proj_kernel<<<NB*NT, ND>>>(x, amp_w, amp_b, phase_w, phase_b);
    scan2_kernel<0><<<NB*2, 256, SCAN_SMEM>>>(cell_l);
    uxconj_kernel<<<NT*NB, 256, UX_SMEM>>>(cell_l);
    scan2_kernel<1><<<NB*2, 256, SCAN_SMEM>>>(cell_l);
    dense_meas_kernel<<<NT*NB, 256>>>(dense_l, meas, out);
}

// round 14
// speedup vs baseline: 1.0092x; 1.0092x over previous
#include <cuda_runtime.h>
#include <math.h>
#include <stdint.h>

#define NB   64
#define NT   128
#define NIN  300
#define ND   64
#define NC   10
#define BETAC 0.8f

typedef unsigned long long u64;

// ---------------- scratch (device globals; no allocations) ----------------
static __device__ float g_W[(size_t)NT*ND*ND];      // W_s = Uh^s, s=1..128 at (s-1)*4096
static __device__ float g_M[(size_t)NT*ND*ND];      // M_t = W_{t+1}^T Ux
static __device__ float g_A[(size_t)NT*ND*ND];      // A_t = M_t W_{t+1}
static __device__ float g_P[(size_t)NT*ND*NC];      // P_t = W_{t+1}^T Wd
static __device__ float g_u1r[NB*NT*ND];
static __device__ float g_u1i[NB*NT*ND];
static __device__ float g_L1r[(size_t)NT*NB*ND*ND]; // tilde-frame layer outputs
static __device__ float g_L1i[(size_t)NT*NB*ND*ND];
static __device__ float g_ux2r[(size_t)NT*NB*ND*ND];
static __device__ float g_ux2i[(size_t)NT*NB*ND*ND];
static __device__ int   g_ready[132];               // W-power ready flags

__device__ __forceinline__ float sigmoidf_(float v) { return 1.0f / (1.0f + expf(-v)); }

// ---- packed f32x2 helpers (sm_103a) ----
__device__ __forceinline__ u64 pk2(float a) {
    u64 r; asm("mov.b64 %0, {%1, %1};" : "=l"(r) : "f"(a)); return r;
}
__device__ __forceinline__ void fma2(u64 &d, u64 a, u64 b) {
    asm("fma.rn.f32x2 %0, %1, %2, %0;" : "+l"(d) : "l"(a), "l"(b));
}
union UF { ulonglong2 u; float4 f; };
#define GETC(v,kk) ((kk)==0?(v).x:((kk)==1?(v).y:((kk)==2?(v).z:(v).w)))

// ---- cluster / DSMEM helpers ----
__device__ __forceinline__ uint32_t smem_u32_(const void* p) {
    uint32_t a;
    asm("{ .reg .u64 t; cvta.to.shared.u64 t, %1; cvt.u32.u64 %0, t; }" : "=r"(a) : "l"(p));
    return a;
}
__device__ __forceinline__ uint32_t mapa_(uint32_t a, uint32_t rank) {
    uint32_t r; asm("mapa.shared::cluster.u32 %0, %1, %2;" : "=r"(r) : "r"(a), "r"(rank));
    return r;
}
__device__ __forceinline__ void stsc16(uint32_t a, float4 v) {
    asm volatile("st.shared::cluster.v4.b32 [%0], {%1,%2,%3,%4};"
        :: "r"(a), "r"(__float_as_uint(v.x)), "r"(__float_as_uint(v.y)),
           "r"(__float_as_uint(v.z)), "r"(__float_as_uint(v.w)) : "memory");
}
__device__ __forceinline__ uint32_t ctarank_() {
    uint32_t r; asm("mov.u32 %0, %%cluster_ctarank;" : "=r"(r)); return r;
}
#define CLUSTER_ARRIVE() asm volatile("barrier.cluster.arrive.aligned;" ::: "memory")
#define CLUSTER_WAIT()   asm volatile("barrier.cluster.wait.aligned;"   ::: "memory")
#define CLUSTER_SYNC() do { CLUSTER_ARRIVE(); CLUSTER_WAIT(); } while(0)

// ---------------- precompute: ALL W powers in ONE kernel (spin flags) ------
__global__ void zero_flags() { if (threadIdx.x < 132) g_ready[threadIdx.x] = 0; }

// CTA i computes W_{i+1}. s>1: W_s = W_base @ W_{s-base}, base = 2^floor(log2(s-1)).
__global__ void __launch_bounds__(256) powers_kernel(const float* __restrict__ Uh) {
    __shared__ float sA[4096], sB[4096];
    const int s   = blockIdx.x + 1;     // 1..128
    const int tid = threadIdx.x;
    if (s == 1) {
        for (int i = tid; i < 4096; i += 256) g_W[i] = Uh[i];
        __threadfence();
        __syncthreads();
        if (tid == 0) atomicExch(&g_ready[1], 1);
        return;
    }
    const int base = 1 << (31 - __clz(s - 1));
    const int j = s - base;
    if (tid == 0) {
        while (atomicAdd(&g_ready[base], 0) == 0) __nanosleep(64);
        while (atomicAdd(&g_ready[j],    0) == 0) __nanosleep(64);
        __threadfence();
    }
    __syncthreads();
    const float* A = g_W + (size_t)(base-1)*4096;
    const float* B = g_W + (size_t)(j-1)*4096;
    float* C = g_W + (size_t)(s-1)*4096;
    for (int i = tid; i < 4096; i += 256) { sA[i] = A[i]; sB[i] = B[i]; }
    __syncthreads();
    const int tx = tid & 15, ty = tid >> 4;
    const int i0 = ty*4, j0 = tx*4;
    float acc[4][4] = {};
    for (int k = 0; k < 64; k++) {
#pragma unroll
        for (int r = 0; r < 4; r++) {
            float a = sA[(i0+r)*64 + k];
#pragma unroll
            for (int c = 0; c < 4; c++) acc[r][c] = fmaf(a, sB[k*64 + j0 + c], acc[r][c]);
        }
    }
#pragma unroll
    for (int r = 0; r < 4; r++)
#pragma unroll
        for (int c = 0; c < 4; c++) C[(i0+r)*64 + j0 + c] = acc[r][c];
    __threadfence();
    __syncthreads();
    if (tid == 0) atomicExch(&g_ready[s], 1);
}

// per t: M_t = W^T Ux ; A_t = M_t W ; P_t = W^T Wd   (W = W_{t+1})
__global__ void __launch_bounds__(256) maps_kernel(const float* __restrict__ Ux,
                                                   const float* __restrict__ Wd) {
    extern __shared__ float dsm[];
    float* sWT = dsm;          // sWT[i*64+k] = W[k][i]
    float* sU  = dsm + 4096;
    float* sM  = dsm + 8192;
    float* sWd = dsm + 12288;  // 640
    const int t = blockIdx.x;
    const float* W = g_W + (size_t)t*4096;
    const int tid = threadIdx.x;
    for (int idx = tid; idx < 4096; idx += 256) {
        sWT[(idx & 63)*64 + (idx >> 6)] = W[idx];
        sU[idx] = Ux[idx];
    }
    for (int idx = tid; idx < 640; idx += 256) sWd[idx] = Wd[idx];
    __syncthreads();
    const int tx = tid & 15, ty = tid >> 4;
    const int i0 = ty*4, j0 = tx*4;
    float acc[4][4] = {};
    for (int k = 0; k < 64; k++) {
#pragma unroll
        for (int r = 0; r < 4; r++) {
            float a = sWT[(i0+r)*64 + k];
#pragma unroll
            for (int c = 0; c < 4; c++) acc[r][c] = fmaf(a, sU[k*64 + j0 + c], acc[r][c]);
        }
    }
#pragma unroll
    for (int r = 0; r < 4; r++)
#pragma unroll
        for (int c = 0; c < 4; c++) {
            sM[(i0+r)*64 + j0 + c] = acc[r][c];
            g_M[(size_t)t*4096 + (i0+r)*64 + j0 + c] = acc[r][c];
        }
    __syncthreads();
    float acc2[4][4] = {};
    for (int k = 0; k < 64; k++) {
#pragma unroll
        for (int r = 0; r < 4; r++) {
            float a = sM[(i0+r)*64 + k];
#pragma unroll
            for (int c = 0; c < 4; c++)  // W[k][j] = sWT[j*64+k]
                acc2[r][c] = fmaf(a, sWT[(j0+c)*64 + k], acc2[r][c]);
        }
    }
#pragma unroll
    for (int r = 0; r < 4; r++)
#pragma unroll
        for (int c = 0; c < 4; c++)
            g_A[(size_t)t*4096 + (i0+r)*64 + j0 + c] = acc2[r][c];
    for (int idx = tid; idx < 640; idx += 256) {
        int i = idx / 10, jj = idx % 10;
        float sum = 0.f;
        for (int k = 0; k < 64; k++) sum = fmaf(sWT[i*64 + k], sWd[k*10 + jj], sum);
        g_P[(size_t)t*640 + idx] = sum;
    }
}

// ---------------- K1: projections + tilde-frame rank-1 vectors -------------
__global__ void proj_kernel(const float* __restrict__ x,
                            const float* __restrict__ amp_w,
                            const float* __restrict__ amp_b,
                            const float* __restrict__ phase_w,
                            const float* __restrict__ phase_b)
{
    __shared__ float xsh[NIN];
    __shared__ float red[ND];
    __shared__ float ssr[ND], ssi[ND];
    __shared__ float sMT[ND*65];
    const int blk = blockIdx.x;      // b*NT + t
    const int t   = blk & (NT-1);
    const int tid = threadIdx.x;
    const float* xrow = x + (size_t)blk * NIN;
    const float* Mt = g_M + (size_t)t*4096;

    for (int i = tid; i < NIN; i += ND) xsh[i] = xrow[i];
    for (int i = tid; i < ND*ND; i += ND) sMT[(i & 63)*65 + (i >> 6)] = Mt[i];
    __syncthreads();

    float a = amp_b[tid], p = phase_b[tid];
#pragma unroll 4
    for (int k = 0; k < NIN; k++) {
        float xv = xsh[k];
        a = fmaf(xv, amp_w[k*ND + tid], a);
        p = fmaf(xv, phase_w[k*ND + tid], p);
    }
    red[tid] = a * a;
    __syncthreads();
    if (tid == 0) {
        float s = 0.f;
        for (int i = 0; i < ND; i++) s += red[i];
        red[0] = 1.0f / sqrtf(s);
    }
    __syncthreads();
    float amp = a * red[0];
    ssr[tid] = amp * cosf(p);
    ssi[tid] = amp * sinf(p);
    __syncthreads();

    float ur = 0.f, ui = 0.f;
#pragma unroll 4
    for (int e = 0; e < ND; e++) {
        float u = sMT[e*65 + tid];     // M_t[tid][e]
        ur = fmaf(u, ssr[e], ur);
        ui = fmaf(u, ssi[e], ui);
    }
    g_u1r[(size_t)blk*ND + tid] = ur;
    g_u1i[(size_t)blk*ND + tid] = ui;
}

// ---------------- K2/K4: tilde-frame clustered scan -------------------------
// Per step: N = lam*X + oml*H (split local/peer around the cluster barrier),
// trace = Frobenius (deterministic), C = N@N (my 32 rows), H' = b*C/tr+(1-b)*N.
#define S_HR0 0
#define S_HI0 4096
#define S_HR1 8192
#define S_HI1 12288
#define S_NR  16384
#define S_NI  20480
#define SCAN2_FLOATS 24576

template<int MODE>
__global__ void __launch_bounds__(256, 1) __cluster_dims__(2, 1, 1)
scan2_kernel(const float* __restrict__ lam_ptr)
{
    extern __shared__ float sm[];
    __shared__ float red[8];

    const uint32_t rank  = ctarank_();
    const uint32_t prank = rank ^ 1u;
    const int b    = blockIdx.x >> 1;
    const int row0 = (int)rank * 32;
    const int tid  = threadIdx.x;
    const int tx = tid & 15, ty = tid >> 4;    // ty 0..15
    const int j0 = tx * 4;
    const int eL = row0 + ty*2;                // 2 local-half rows
    const int eP = (row0 ^ 32) + ty*2;         // 2 peer-half rows
    const int g0 = row0 + ty * 2;              // my output rows (2 per thread)
    const float lam = sigmoidf_(lam_ptr[0]);
    const float oml = 1.0f - lam;
    const float ob  = 1.0f - BETAC;
    float* sNr = sm + S_NR;
    float* sNi = sm + S_NI;

    for (int i = tid; i < 4096; i += 256) {
        sm[S_HR0 + i] = ((i >> 6) == (i & 63)) ? (1.0f/ND) : 0.0f;
        sm[S_HI0 + i] = 0.0f;
    }
    __syncthreads();
    const uint32_t myBase = smem_u32_(sm);
    const uint32_t pBase  = mapa_(myBase, prank);

    CLUSTER_ARRIVE();   // pairs with step-0 WAIT

    for (int t = 0; t < NT; t++) {
        const int p = t & 1;
        float* sHr = sm + (p ? S_HR1 : S_HR0);   // read buffer
        float* sHi = sm + (p ? S_HI1 : S_HI0);
        float* dHr = sm + (p ? S_HR0 : S_HR1);   // write buffer
        float* dHi = sm + (p ? S_HI0 : S_HI1);
        const uint32_t pdHr = pBase + (uint32_t)(p ? S_HR0 : S_HR1) * 4u;
        const uint32_t pdHi = pBase + (uint32_t)(p ? S_HI0 : S_HI1) * 4u;

        // prefetch X for my 4 N-rows (2 local + 2 peer)
        float4 xLr[2], xLi[2], xPr[2], xPi[2];
        float4 vrj, vij; float vreL[2], vieL[2], vreP[2], vieP[2];
        if (MODE == 1) {
            const size_t base = ((size_t)t*NB + b)*4096;
#pragma unroll
            for (int rr = 0; rr < 2; rr++) {
                xLr[rr] = *(const float4*)&g_ux2r[base + (size_t)(eL+rr)*64 + j0];
                xLi[rr] = *(const float4*)&g_ux2i[base + (size_t)(eL+rr)*64 + j0];
                xPr[rr] = *(const float4*)&g_ux2r[base + (size_t)(eP+rr)*64 + j0];
                xPi[rr] = *(const float4*)&g_ux2i[base + (size_t)(eP+rr)*64 + j0];
            }
        } else {
            const float* ur = g_u1r + ((size_t)b*NT + t)*ND;
            const float* ui = g_u1i + ((size_t)b*NT + t)*ND;
            vrj = *(const float4*)&ur[j0];
            vij = *(const float4*)&ui[j0];
#pragma unroll
            for (int rr = 0; rr < 2; rr++) {
                vreL[rr] = ur[eL+rr]; vieL[rr] = ui[eL+rr];
                vreP[rr] = ur[eP+rr]; vieP[rr] = ui[eP+rr];
            }
        }

        // ---- N local-half rows (sHr local rows visible from prev-step sync) ----
        float sq = 0.f;
#pragma unroll
        for (int rr = 0; rr < 2; rr++) {
            const int e = eL + rr;
            float4 hr = *(const float4*)&sHr[e*64 + j0];
            float4 hi = *(const float4*)&sHi[e*64 + j0];
            float4 nr, ni;
            if (MODE == 0) {
                nr.x = fmaf(oml, hr.x, lam*(vreL[rr]*vrj.x + vieL[rr]*vij.x));
                nr.y = fmaf(oml, hr.y, lam*(vreL[rr]*vrj.y + vieL[rr]*vij.y));
                nr.z = fmaf(oml, hr.z, lam*(vreL[rr]*vrj.z + vieL[rr]*vij.z));
                nr.w = fmaf(oml, hr.w, lam*(vreL[rr]*vrj.w + vieL[rr]*vij.w));
                ni.x = fmaf(oml, hi.x, lam*(vieL[rr]*vrj.x - vreL[rr]*vij.x));
                ni.y = fmaf(oml, hi.y, lam*(vieL[rr]*vrj.y - vreL[rr]*vij.y));
                ni.z = fmaf(oml, hi.z, lam*(vieL[rr]*vrj.z - vreL[rr]*vij.z));
                ni.w = fmaf(oml, hi.w, lam*(vieL[rr]*vrj.w - vreL[rr]*vij.w));
            } else {
                nr.x = fmaf(oml, hr.x, xLr[rr].x);
                nr.y = fmaf(oml, hr.y, xLr[rr].y);
                nr.z = fmaf(oml, hr.z, xLr[rr].z);
                nr.w = fmaf(oml, hr.w, xLr[rr].w);
                ni.x = fmaf(oml, hi.x, xLi[rr].x);
                ni.y = fmaf(oml, hi.y, xLi[rr].y);
                ni.z = fmaf(oml, hi.z, xLi[rr].z);
                ni.w = fmaf(oml, hi.w, xLi[rr].w);
            }
            *(float4*)&sNr[e*64 + j0] = nr;
            *(float4*)&sNi[e*64 + j0] = ni;
            sq = fmaf(nr.x, nr.x, sq); sq = fmaf(nr.y, nr.y, sq);
            sq = fmaf(nr.z, nr.z, sq); sq = fmaf(nr.w, nr.w, sq);
            sq = fmaf(ni.x, ni.x, sq); sq = fmaf(ni.y, ni.y, sq);
            sq = fmaf(ni.z, ni.z, sq); sq = fmaf(ni.w, ni.w, sq);
        }

        CLUSTER_WAIT();    // peer H rows (prev step) have arrived

        // ---- N peer-half rows ----
#pragma unroll
        for (int rr = 0; rr < 2; rr++) {
            const int e = eP + rr;
            float4 hr = *(const float4*)&sHr[e*64 + j0];
            float4 hi = *(const float4*)&sHi[e*64 + j0];
            float4 nr, ni;
            if (MODE == 0) {
                nr.x = fmaf(oml, hr.x, lam*(vreP[rr]*vrj.x + vieP[rr]*vij.x));
                nr.y = fmaf(oml, hr.y, lam*(vreP[rr]*vrj.y + vieP[rr]*vij.y));
                nr.z = fmaf(oml, hr.z, lam*(vreP[rr]*vrj.z + vieP[rr]*vij.z));
                nr.w = fmaf(oml, hr.w, lam*(vreP[rr]*vrj.w + vieP[rr]*vij.w));
                ni.x = fmaf(oml, hi.x, lam*(vieP[rr]*vrj.x - vreP[rr]*vij.x));
                ni.y = fmaf(oml, hi.y, lam*(vieP[rr]*vrj.y - vreP[rr]*vij.y));
                ni.z = fmaf(oml, hi.z, lam*(vieP[rr]*vrj.z - vreP[rr]*vij.z));
                ni.w = fmaf(oml, hi.w, lam*(vieP[rr]*vrj.w - vreP[rr]*vij.w));
            } else {
                nr.x = fmaf(oml, hr.x, xPr[rr].x);
                nr.y = fmaf(oml, hr.y, xPr[rr].y);
                nr.z = fmaf(oml, hr.z, xPr[rr].z);
                nr.w = fmaf(oml, hr.w, xPr[rr].w);
                ni.x = fmaf(oml, hi.x, xPi[rr].x);
                ni.y = fmaf(oml, hi.y, xPi[rr].y);
                ni.z = fmaf(oml, hi.z, xPi[rr].z);
                ni.w = fmaf(oml, hi.w, xPi[rr].w);
            }
            *(float4*)&sNr[e*64 + j0] = nr;
            *(float4*)&sNi[e*64 + j0] = ni;
            sq = fmaf(nr.x, nr.x, sq); sq = fmaf(nr.y, nr.y, sq);
            sq = fmaf(nr.z, nr.z, sq); sq = fmaf(nr.w, nr.w, sq);
            sq = fmaf(ni.x, ni.x, sq); sq = fmaf(ni.y, ni.y, sq);
            sq = fmaf(ni.z, ni.z, sq); sq = fmaf(ni.w, ni.w, sq);
        }
        // deterministic reduce: warp tree -> red[8] -> fixed-order sum
#pragma unroll
        for (int o = 16; o > 0; o >>= 1)
            sq += __shfl_down_sync(0xffffffffu, sq, o);
        if ((tid & 31) == 0) red[tid >> 5] = sq;
        __syncthreads();   // sN + red visible
        const float tr = ((((((red[0]+red[1])+red[2])+red[3])+red[4])+red[5])+red[6])+red[7];

        // ---- C[myrows,:] = N[myrows,:] @ N (complex square), grouped b-loads ----
        UF cR[2], cI[2];
#pragma unroll
        for (int r = 0; r < 2; r++) { cR[r].f = make_float4(0,0,0,0); cI[r].f = make_float4(0,0,0,0); }
#pragma unroll 2
        for (int k0 = 0; k0 < 64; k0 += 4) {
            UF br[4], bi[4];
#pragma unroll
            for (int kk = 0; kk < 4; kk++) {
                br[kk].f = *(const float4*)&sNr[(k0+kk)*64 + j0];
                bi[kk].f = *(const float4*)&sNi[(k0+kk)*64 + j0];
            }
            float4 ar4[2], ai4[2];
#pragma unroll
            for (int r = 0; r < 2; r++) {
                ar4[r] = *(const float4*)&sNr[(g0+r)*64 + k0];
                ai4[r] = *(const float4*)&sNi[(g0+r)*64 + k0];
            }
#pragma unroll
            for (int kk = 0; kk < 4; kk++) {
#pragma unroll
                for (int r = 0; r < 2; r++) {
                    float av  = GETC(ar4[r], kk);
                    float avi = GETC(ai4[r], kk);
                    u64 arp = pk2(av);
                    u64 aip = pk2(avi);
                    u64 ain = pk2(-avi);
                    fma2(cR[r].u.x, arp, br[kk].u.x); fma2(cR[r].u.y, arp, br[kk].u.y);
                    fma2(cR[r].u.x, ain, bi[kk].u.x); fma2(cR[r].u.y, ain, bi[kk].u.y);
                    fma2(cI[r].u.x, arp, bi[kk].u.x); fma2(cI[r].u.y, arp, bi[kk].u.y);
                    fma2(cI[r].u.x, aip, br[kk].u.x); fma2(cI[r].u.y, aip, br[kk].u.y);
                }
            }
        }

        // ---- epilogue: H' = b*C/tr + (1-b)*N ; local + peer + gmem ----
        const float sc = BETAC / tr;
        float* gr = g_L1r + ((size_t)t*NB + b)*4096;
        float* gi = g_L1i + ((size_t)t*NB + b)*4096;
#pragma unroll
        for (int rr = 0; rr < 2; rr++) {
            const int g = g0 + rr;
            float4 nr = *(const float4*)&sNr[g*64 + j0];
            float4 ni = *(const float4*)&sNi[g*64 + j0];
            float4 hR, hI;
            hR.x = fmaf(sc, cR[rr].f.x, ob*nr.x);  hR.y = fmaf(sc, cR[rr].f.y, ob*nr.y);
            hR.z = fmaf(sc, cR[rr].f.z, ob*nr.z);  hR.w = fmaf(sc, cR[rr].f.w, ob*nr.w);
            hI.x = fmaf(sc, cI[rr].f.x, ob*ni.x);  hI.y = fmaf(sc, cI[rr].f.y, ob*ni.y);
            hI.z = fmaf(sc, cI[rr].f.z, ob*ni.z);  hI.w = fmaf(sc, cI[rr].f.w, ob*ni.w);
            *(float4*)&dHr[g*64 + j0] = hR;
            *(float4*)&dHi[g*64 + j0] = hI;
            stsc16(pdHr + (uint32_t)(g*64 + j0)*4u, hR);
            stsc16(pdHi + (uint32_t)(g*64 + j0)*4u, hI);
            *(float4*)&gr[g*64 + j0] = hR;
            *(float4*)&gi[g*64 + j0] = hI;
        }
        __syncthreads();   // local H writes visible CTA-wide
        CLUSTER_ARRIVE();  // release H stores to peer
    }

    CLUSTER_WAIT();
    CLUSTER_SYNC();        // no exit while peer DSMEM stores in flight
}

// ---------------- K3: layer-2 x-side conjugation (tilde frame, A_t) --------
__global__ void __launch_bounds__(256) uxconj_kernel(const float* __restrict__ lam_ptr)
{
    extern __shared__ float sm[];
    float* sUx  = sm;
    float* sUxT = sm + 4096;
    float* sXr  = sm + 8192;
    float* sXi  = sm + 12288;
    float* sTr  = sm + 16384;
    float* sTi  = sm + 20480;
    const int tid = threadIdx.x;
    const int tx = tid & 15, ty = tid >> 4;
    const int i0 = ty * 4;
    const float lam = sigmoidf_(lam_ptr[0]);
    const size_t base = (size_t)blockIdx.x * 4096;
    const float* At = g_A + (size_t)(blockIdx.x >> 6) * 4096;   // blk = t*NB+b

    for (int i = tid; i < ND*ND; i += 256) {
        float v = At[i];
        sUx[i] = v;
        sUxT[(i & 63)*64 + (i >> 6)] = v;
        sXr[i] = g_L1r[base + i];
        sXi[i] = g_L1i[base + i];
    }
    __syncthreads();

    {
        UF aR[4], aI[4];
#pragma unroll
        for (int r = 0; r < 4; r++) { aR[r].f = make_float4(0,0,0,0); aI[r].f = make_float4(0,0,0,0); }
        const ulonglong2* xr2 = (const ulonglong2*)sXr;
        const ulonglong2* xi2 = (const ulonglong2*)sXi;
#pragma unroll 2
        for (int k0 = 0; k0 < ND; k0 += 4) {
            ulonglong2 br[4], bi[4];
#pragma unroll
            for (int kk = 0; kk < 4; kk++) {
                br[kk] = xr2[(k0+kk)*16 + tx];
                bi[kk] = xi2[(k0+kk)*16 + tx];
            }
            float4 a4[4];
#pragma unroll
            for (int r = 0; r < 4; r++) a4[r] = *(const float4*)&sUx[(i0+r)*64 + k0];
#pragma unroll
            for (int kk = 0; kk < 4; kk++) {
#pragma unroll
                for (int r = 0; r < 4; r++) {
                    u64 ap = pk2(GETC(a4[r], kk));
                    fma2(aR[r].u.x, ap, br[kk].x); fma2(aR[r].u.y, ap, br[kk].y);
                    fma2(aI[r].u.x, ap, bi[kk].x); fma2(aI[r].u.y, ap, bi[kk].y);
                }
            }
        }
#pragma unroll
        for (int r = 0; r < 4; r++) {
            ((float4*)sTr)[(i0+r)*16 + tx] = aR[r].f;
            ((float4*)sTi)[(i0+r)*16 + tx] = aI[r].f;
        }
    }
    __syncthreads();

    {
        UF oR[4], oI[4];
#pragma unroll
        for (int r = 0; r < 4; r++) { oR[r].f = make_float4(0,0,0,0); oI[r].f = make_float4(0,0,0,0); }
        const ulonglong2* uxT2 = (const ulonglong2*)sUxT;
#pragma unroll 2
        for (int k0 = 0; k0 < ND; k0 += 4) {
            ulonglong2 b4[4];
#pragma unroll
            for (int kk = 0; kk < 4; kk++) b4[kk] = uxT2[(k0+kk)*16 + tx];
            float4 ar4[4], ai4[4];
#pragma unroll
            for (int r = 0; r < 4; r++) {
                ar4[r] = *(const float4*)&sTr[(i0+r)*64 + k0];
                ai4[r] = *(const float4*)&sTi[(i0+r)*64 + k0];
            }
#pragma unroll
            for (int kk = 0; kk < 4; kk++) {
#pragma unroll
                for (int r = 0; r < 4; r++) {
                    u64 arp = pk2(GETC(ar4[r], kk));
                    u64 aip = pk2(GETC(ai4[r], kk));
                    fma2(oR[r].u.x, arp, b4[kk].x); fma2(oR[r].u.y, arp, b4[kk].y);
                    fma2(oI[r].u.x, aip, b4[kk].x); fma2(oI[r].u.y, aip, b4[kk].y);
                }
            }
        }
        float4* gr = (float4*)(g_ux2r + base);
        float4* gi = (float4*)(g_ux2i + base);
#pragma unroll
        for (int r = 0; r < 4; r++) {
            float4 vR = oR[r].f, vI = oI[r].f;
            vR.x *= lam; vR.y *= lam; vR.z *= lam; vR.w *= lam;
            vI.x *= lam; vI.y *= lam; vI.z *= lam; vI.w *= lam;
            gr[(i0+r)*16 + tx] = vR;
            gi[(i0+r)*16 + tx] = vI;
        }
    }
}

// ---------------- K5: dense + measurement + log (tilde frame, P_t) ---------
__global__ void __launch_bounds__(256) dense_meas_kernel(const float* __restrict__ dlam_ptr,
                                                         const float* __restrict__ mk,
                                                         float* __restrict__ out)
{
    __shared__ float sRr[ND*ND], sRi[ND*ND];
    __shared__ float sW[ND*NC];
    __shared__ float tmpr[ND*NC], tmpi[ND*NC];
    __shared__ float sgr[NC*NC], sgi[NC*NC];
    __shared__ float svr[NC*NC], svi[NC*NC];
    const int blk = blockIdx.x;     // t*NB + b
    const int tid = threadIdx.x;
    const size_t base = (size_t)blk * 4096;
    const float* Pt = g_P + (size_t)(blk >> 6) * 640;

    for (int i = tid; i < ND*ND; i += 256) { sRr[i] = g_L1r[base + i]; sRi[i] = g_L1i[base + i]; }
    for (int i = tid; i < ND*NC; i += 256) sW[i] = Pt[i];
    if (tid < NC) {
        float nrm = 0.f;
        for (int c = 0; c < NC; c++) {
            float vr = mk[(tid*NC + c)*2 + 0];
            float vi = mk[(tid*NC + c)*2 + 1];
            nrm += vr*vr + vi*vi;
        }
        float inv = 1.0f / sqrtf(nrm);
        for (int c = 0; c < NC; c++) {
            svr[tid*NC + c] = mk[(tid*NC + c)*2 + 0] * inv;
            svi[tid*NC + c] = mk[(tid*NC + c)*2 + 1] * inv;
        }
    }
    __syncthreads();

    for (int idx = tid; idx < ND*NC; idx += 256) {
        int d = idx / NC, c = idx % NC;
        float ar = 0.f, ai = 0.f;
#pragma unroll 4
        for (int e = 0; e < ND; e++) {
            float w = sW[e*NC + c];
            ar = fmaf(sRr[d*64 + e], w, ar);
            ai = fmaf(sRi[d*64 + e], w, ai);
        }
        tmpr[idx] = ar; tmpi[idx] = ai;
    }
    __syncthreads();

    if (tid < NC*NC) {
        int c = tid / NC, f = tid % NC;
        float ar = 0.f, ai = 0.f;
#pragma unroll 4
        for (int d = 0; d < ND; d++) {
            float w = sW[d*NC + c];
            ar = fmaf(w, tmpr[d*NC + f], ar);
            ai = fmaf(w, tmpi[d*NC + f], ai);
        }
        float dlam = sigmoidf_(dlam_ptr[0]);
        ar = dlam * ar + ((c == f) ? (1.0f - dlam) / NC : 0.0f);
        ai = dlam * ai;
        sgr[tid] = ar; sgi[tid] = ai;
    }
    __syncthreads();

    if (tid < NC) {
        float tr = 0.f;
        for (int c = 0; c < NC; c++) tr += sgr[c*NC + c];
        float invtr = 1.0f / tr;
        int k = tid;
        float p = 0.f;
        for (int c = 0; c < NC; c++) {
            float vrc = svr[k*NC + c], vic = svi[k*NC + c];
            for (int d = 0; d < NC; d++) {
                float vrd = svr[k*NC + d], vid = svi[k*NC + d];
                p += (vrc*vrd + vic*vid) * sgr[c*NC + d]
                   + (vic*vrd - vrc*vid) * sgi[c*NC + d];
            }
        }
        p *= invtr;
        int t = blk / NB, b = blk % NB;
        out[((size_t)b*NT + t)*NC + k] = logf(p);
    }
}

// ---------------- launch ----------------
extern "C" void kernel_launch(void* const* d_in, const int* in_sizes, int n_in,
                              void* d_out, int out_size)
{
    const float* x        = (const float*)d_in[0];
    const float* amp_w    = (const float*)d_in[1];
    const float* amp_b    = (const float*)d_in[2];
    const float* phase_w  = (const float*)d_in[3];
    const float* phase_b  = (const float*)d_in[4];
    const float* Ux       = (const float*)d_in[5];
    const float* Uh       = (const float*)d_in[6];
    const float* cell_l   = (const float*)d_in[7];
    const float* dense_w  = (const float*)d_in[8];
    const float* dense_l  = (const float*)d_in[9];
    const float* meas     = (const float*)d_in[10];
    float* out = (float*)d_out;

    const int SCAN_SMEM = SCAN2_FLOATS * 4;      // 96 KB
    const int UX_SMEM   = 6 * 4096 * 4;          // 96 KB
    const int MAPS_SMEM = (3*4096 + 640) * 4;    // ~51.7 KB
    cudaFuncSetAttribute(scan2_kernel<0>, cudaFuncAttributeMaxDynamicSharedMemorySize, SCAN_SMEM);
    cudaFuncSetAttribute(scan2_kernel<1>, cudaFuncAttributeMaxDynamicSharedMemorySize, SCAN_SMEM);
    cudaFuncSetAttribute(uxconj_kernel,   cudaFuncAttributeMaxDynamicSharedMemorySize, UX_SMEM);
    cudaFuncSetAttribute(maps_kernel,     cudaFuncAttributeMaxDynamicSharedMemorySize, MAPS_SMEM);

    // precompute all W powers in one launch (log-depth via ready flags)
    zero_flags<<<1, 256>>>();
    powers_kernel<<<NT, 256>>>(Uh);
    maps_kernel<<<NT, 256, MAPS_SMEM>>>(Ux, dense_w);

    proj_kernel<<<NB*NT, ND>>>(x, amp_w, amp_b, phase_w, phase_b);
    scan2_kernel<0><<<NB*2, 256, SCAN_SMEM>>>(cell_l);
    uxconj_kernel<<<NT*NB, 256, UX_SMEM>>>(cell_l);
    scan2_kernel<1><<<NB*2, 256, SCAN_SMEM>>>(cell_l);
    dense_meas_kernel<<<NT*NB, 256>>>(dense_l, meas, out);
}

// round 15
// speedup vs baseline: 1.0112x; 1.0020x over previous
#include <cuda_runtime.h>
#include <math.h>
#include <stdint.h>

#define NB   64
#define NT   128
#define NIN  300
#define ND   64
#define NC   10
#define BETAC 0.8f

typedef unsigned long long u64;

// ---------------- scratch (device globals; no allocations) ----------------
static __device__ float g_W[(size_t)NT*ND*ND];      // W_s = Uh^s, s=1..128 at (s-1)*4096
static __device__ float g_M[(size_t)NT*ND*ND];      // M_t = W_{t+1}^T Ux
static __device__ float g_A[(size_t)NT*ND*ND];      // A_t = M_t W_{t+1}
static __device__ float g_P[(size_t)NT*ND*NC];      // P_t = W_{t+1}^T Wd
static __device__ float g_u1r[NB*NT*ND];
static __device__ float g_u1i[NB*NT*ND];
static __device__ float g_L1r[(size_t)NT*NB*ND*ND]; // tilde-frame layer outputs
static __device__ float g_L1i[(size_t)NT*NB*ND*ND];
static __device__ float g_ux2r[(size_t)NT*NB*ND*ND];
static __device__ float g_ux2i[(size_t)NT*NB*ND*ND];
static __device__ int   g_ready[132];               // W-power ready flags

__device__ __forceinline__ float sigmoidf_(float v) { return 1.0f / (1.0f + expf(-v)); }

// ---- packed f32x2 helpers (sm_103a) ----
__device__ __forceinline__ u64 pk2(float a) {
    u64 r; asm("mov.b64 %0, {%1, %1};" : "=l"(r) : "f"(a)); return r;
}
__device__ __forceinline__ void fma2(u64 &d, u64 a, u64 b) {
    asm("fma.rn.f32x2 %0, %1, %2, %0;" : "+l"(d) : "l"(a), "l"(b));
}
union UF { ulonglong2 u; float4 f; };
#define GETC(v,kk) ((kk)==0?(v).x:((kk)==1?(v).y:((kk)==2?(v).z:(v).w)))

// ---- cluster / DSMEM helpers ----
__device__ __forceinline__ uint32_t smem_u32_(const void* p) {
    uint32_t a;
    asm("{ .reg .u64 t; cvta.to.shared.u64 t, %1; cvt.u32.u64 %0, t; }" : "=r"(a) : "l"(p));
    return a;
}
__device__ __forceinline__ uint32_t mapa_(uint32_t a, uint32_t rank) {
    uint32_t r; asm("mapa.shared::cluster.u32 %0, %1, %2;" : "=r"(r) : "r"(a), "r"(rank));
    return r;
}
__device__ __forceinline__ void stsc16(uint32_t a, float4 v) {
    asm volatile("st.shared::cluster.v4.b32 [%0], {%1,%2,%3,%4};"
        :: "r"(a), "r"(__float_as_uint(v.x)), "r"(__float_as_uint(v.y)),
           "r"(__float_as_uint(v.z)), "r"(__float_as_uint(v.w)) : "memory");
}
__device__ __forceinline__ uint32_t ctarank_() {
    uint32_t r; asm("mov.u32 %0, %%cluster_ctarank;" : "=r"(r)); return r;
}
#define CLUSTER_ARRIVE() asm volatile("barrier.cluster.arrive.aligned;" ::: "memory")
#define CLUSTER_WAIT()   asm volatile("barrier.cluster.wait.aligned;"   ::: "memory")
#define CLUSTER_SYNC() do { CLUSTER_ARRIVE(); CLUSTER_WAIT(); } while(0)

// ---------------- precompute: ALL W powers in ONE kernel (spin flags) ------
__global__ void zero_flags() { if (threadIdx.x < 132) g_ready[threadIdx.x] = 0; }

// CTA i computes W_{i+1}. s>1: W_s = W_base @ W_{s-base}, base = 2^floor(log2(s-1)).
__global__ void __launch_bounds__(256) powers_kernel(const float* __restrict__ Uh) {
    __shared__ float sA[4096], sB[4096];
    const int s   = blockIdx.x + 1;     // 1..128
    const int tid = threadIdx.x;
    if (s == 1) {
        for (int i = tid; i < 4096; i += 256) g_W[i] = Uh[i];
        __threadfence();
        __syncthreads();
        if (tid == 0) atomicExch(&g_ready[1], 1);
        return;
    }
    const int base = 1 << (31 - __clz(s - 1));
    const int j = s - base;
    if (tid == 0) {
        while (atomicAdd(&g_ready[base], 0) == 0) __nanosleep(64);
        while (atomicAdd(&g_ready[j],    0) == 0) __nanosleep(64);
        __threadfence();
    }
    __syncthreads();
    const float* A = g_W + (size_t)(base-1)*4096;
    const float* B = g_W + (size_t)(j-1)*4096;
    float* C = g_W + (size_t)(s-1)*4096;
    for (int i = tid; i < 4096; i += 256) { sA[i] = A[i]; sB[i] = B[i]; }
    __syncthreads();
    const int tx = tid & 15, ty = tid >> 4;
    const int i0 = ty*4, j0 = tx*4;
    float acc[4][4] = {};
    for (int k = 0; k < 64; k++) {
#pragma unroll
        for (int r = 0; r < 4; r++) {
            float a = sA[(i0+r)*64 + k];
#pragma unroll
            for (int c = 0; c < 4; c++) acc[r][c] = fmaf(a, sB[k*64 + j0 + c], acc[r][c]);
        }
    }
#pragma unroll
    for (int r = 0; r < 4; r++)
#pragma unroll
        for (int c = 0; c < 4; c++) C[(i0+r)*64 + j0 + c] = acc[r][c];
    __threadfence();
    __syncthreads();
    if (tid == 0) atomicExch(&g_ready[s], 1);
}

// per t: M_t = W^T Ux ; A_t = M_t W ; P_t = W^T Wd   (W = W_{t+1})
__global__ void __launch_bounds__(256) maps_kernel(const float* __restrict__ Ux,
                                                   const float* __restrict__ Wd) {
    extern __shared__ float dsm[];
    float* sWT = dsm;          // sWT[i*64+k] = W[k][i]
    float* sU  = dsm + 4096;
    float* sM  = dsm + 8192;
    float* sWd = dsm + 12288;  // 640
    const int t = blockIdx.x;
    const float* W = g_W + (size_t)t*4096;
    const int tid = threadIdx.x;
    for (int idx = tid; idx < 4096; idx += 256) {
        sWT[(idx & 63)*64 + (idx >> 6)] = W[idx];
        sU[idx] = Ux[idx];
    }
    for (int idx = tid; idx < 640; idx += 256) sWd[idx] = Wd[idx];
    __syncthreads();
    const int tx = tid & 15, ty = tid >> 4;
    const int i0 = ty*4, j0 = tx*4;
    float acc[4][4] = {};
    for (int k = 0; k < 64; k++) {
#pragma unroll
        for (int r = 0; r < 4; r++) {
            float a = sWT[(i0+r)*64 + k];
#pragma unroll
            for (int c = 0; c < 4; c++) acc[r][c] = fmaf(a, sU[k*64 + j0 + c], acc[r][c]);
        }
    }
#pragma unroll
    for (int r = 0; r < 4; r++)
#pragma unroll
        for (int c = 0; c < 4; c++) {
            sM[(i0+r)*64 + j0 + c] = acc[r][c];
            g_M[(size_t)t*4096 + (i0+r)*64 + j0 + c] = acc[r][c];
        }
    __syncthreads();
    float acc2[4][4] = {};
    for (int k = 0; k < 64; k++) {
#pragma unroll
        for (int r = 0; r < 4; r++) {
            float a = sM[(i0+r)*64 + k];
#pragma unroll
            for (int c = 0; c < 4; c++)  // W[k][j] = sWT[j*64+k]
                acc2[r][c] = fmaf(a, sWT[(j0+c)*64 + k], acc2[r][c]);
        }
    }
#pragma unroll
    for (int r = 0; r < 4; r++)
#pragma unroll
        for (int c = 0; c < 4; c++)
            g_A[(size_t)t*4096 + (i0+r)*64 + j0 + c] = acc2[r][c];
    for (int idx = tid; idx < 640; idx += 256) {
        int i = idx / 10, jj = idx % 10;
        float sum = 0.f;
        for (int k = 0; k < 64; k++) sum = fmaf(sWT[i*64 + k], sWd[k*10 + jj], sum);
        g_P[(size_t)t*640 + idx] = sum;
    }
}

// ---------------- K1: projections + tilde-frame rank-1 vectors -------------
__global__ void proj_kernel(const float* __restrict__ x,
                            const float* __restrict__ amp_w,
                            const float* __restrict__ amp_b,
                            const float* __restrict__ phase_w,
                            const float* __restrict__ phase_b)
{
    __shared__ float xsh[NIN];
    __shared__ float red[ND];
    __shared__ float ssr[ND], ssi[ND];
    __shared__ float sMT[ND*65];
    const int blk = blockIdx.x;      // b*NT + t
    const int t   = blk & (NT-1);
    const int tid = threadIdx.x;
    const float* xrow = x + (size_t)blk * NIN;
    const float* Mt = g_M + (size_t)t*4096;

    for (int i = tid; i < NIN; i += ND) xsh[i] = xrow[i];
    for (int i = tid; i < ND*ND; i += ND) sMT[(i & 63)*65 + (i >> 6)] = Mt[i];
    __syncthreads();

    float a = amp_b[tid], p = phase_b[tid];
#pragma unroll 4
    for (int k = 0; k < NIN; k++) {
        float xv = xsh[k];
        a = fmaf(xv, amp_w[k*ND + tid], a);
        p = fmaf(xv, phase_w[k*ND + tid], p);
    }
    red[tid] = a * a;
    __syncthreads();
    if (tid == 0) {
        float s = 0.f;
        for (int i = 0; i < ND; i++) s += red[i];
        red[0] = 1.0f / sqrtf(s);
    }
    __syncthreads();
    float amp = a * red[0];
    ssr[tid] = amp * cosf(p);
    ssi[tid] = amp * sinf(p);
    __syncthreads();

    float ur = 0.f, ui = 0.f;
#pragma unroll 4
    for (int e = 0; e < ND; e++) {
        float u = sMT[e*65 + tid];     // M_t[tid][e]
        ur = fmaf(u, ssr[e], ur);
        ui = fmaf(u, ssi[e], ui);
    }
    g_u1r[(size_t)blk*ND + tid] = ur;
    g_u1i[(size_t)blk*ND + tid] = ui;
}

// ---------------- K2/K4: tilde-frame clustered scan -------------------------
// Per step: N = lam*X + oml*H (split local/peer around the cluster barrier),
// trace = Frobenius (deterministic), C = N@N (my 32 rows), H' = b*C/tr+(1-b)*N.
#define S_HR0 0
#define S_HI0 4096
#define S_HR1 8192
#define S_HI1 12288
#define S_NR  16384
#define S_NI  20480
#define SCAN2_FLOATS 24576

template<int MODE>
__global__ void __launch_bounds__(256, 1) __cluster_dims__(2, 1, 1)
scan2_kernel(const float* __restrict__ lam_ptr)
{
    extern __shared__ float sm[];
    __shared__ float red[8];

    const uint32_t rank  = ctarank_();
    const uint32_t prank = rank ^ 1u;
    const int b    = blockIdx.x >> 1;
    const int row0 = (int)rank * 32;
    const int tid  = threadIdx.x;
    const int tx = tid & 15, ty = tid >> 4;    // ty 0..15
    const int j0 = tx * 4;
    const int eL = row0 + ty*2;                // 2 local-half rows
    const int eP = (row0 ^ 32) + ty*2;         // 2 peer-half rows
    const int g0 = row0 + ty * 2;              // my output rows (2 per thread)
    const float lam = sigmoidf_(lam_ptr[0]);
    const float oml = 1.0f - lam;
    const float ob  = 1.0f - BETAC;
    float* sNr = sm + S_NR;
    float* sNi = sm + S_NI;

    for (int i = tid; i < 4096; i += 256) {
        sm[S_HR0 + i] = ((i >> 6) == (i & 63)) ? (1.0f/ND) : 0.0f;
        sm[S_HI0 + i] = 0.0f;
    }
    __syncthreads();
    const uint32_t myBase = smem_u32_(sm);
    const uint32_t pBase  = mapa_(myBase, prank);

    CLUSTER_ARRIVE();   // pairs with step-0 WAIT

    for (int t = 0; t < NT; t++) {
        const int p = t & 1;
        float* sHr = sm + (p ? S_HR1 : S_HR0);   // read buffer
        float* sHi = sm + (p ? S_HI1 : S_HI0);
        float* dHr = sm + (p ? S_HR0 : S_HR1);   // write buffer
        float* dHi = sm + (p ? S_HI0 : S_HI1);
        const uint32_t pdHr = pBase + (uint32_t)(p ? S_HR0 : S_HR1) * 4u;
        const uint32_t pdHi = pBase + (uint32_t)(p ? S_HI0 : S_HI1) * 4u;

        // prefetch X for my 4 N-rows (2 local + 2 peer)
        float4 xLr[2], xLi[2], xPr[2], xPi[2];
        float4 vrj, vij; float vreL[2], vieL[2], vreP[2], vieP[2];
        if (MODE == 1) {
            const size_t base = ((size_t)t*NB + b)*4096;
#pragma unroll
            for (int rr = 0; rr < 2; rr++) {
                xLr[rr] = *(const float4*)&g_ux2r[base + (size_t)(eL+rr)*64 + j0];
                xLi[rr] = *(const float4*)&g_ux2i[base + (size_t)(eL+rr)*64 + j0];
                xPr[rr] = *(const float4*)&g_ux2r[base + (size_t)(eP+rr)*64 + j0];
                xPi[rr] = *(const float4*)&g_ux2i[base + (size_t)(eP+rr)*64 + j0];
            }
        } else {
            const float* ur = g_u1r + ((size_t)b*NT + t)*ND;
            const float* ui = g_u1i + ((size_t)b*NT + t)*ND;
            vrj = *(const float4*)&ur[j0];
            vij = *(const float4*)&ui[j0];
#pragma unroll
            for (int rr = 0; rr < 2; rr++) {
                vreL[rr] = ur[eL+rr]; vieL[rr] = ui[eL+rr];
                vreP[rr] = ur[eP+rr]; vieP[rr] = ui[eP+rr];
            }
        }

        // ---- N local-half rows (sHr local rows visible from prev-step sync) ----
        float sq = 0.f;
#pragma unroll
        for (int rr = 0; rr < 2; rr++) {
            const int e = eL + rr;
            float4 hr = *(const float4*)&sHr[e*64 + j0];
            float4 hi = *(const float4*)&sHi[e*64 + j0];
            float4 nr, ni;
            if (MODE == 0) {
                nr.x = fmaf(oml, hr.x, lam*(vreL[rr]*vrj.x + vieL[rr]*vij.x));
                nr.y = fmaf(oml, hr.y, lam*(vreL[rr]*vrj.y + vieL[rr]*vij.y));
                nr.z = fmaf(oml, hr.z, lam*(vreL[rr]*vrj.z + vieL[rr]*vij.z));
                nr.w = fmaf(oml, hr.w, lam*(vreL[rr]*vrj.w + vieL[rr]*vij.w));
                ni.x = fmaf(oml, hi.x, lam*(vieL[rr]*vrj.x - vreL[rr]*vij.x));
                ni.y = fmaf(oml, hi.y, lam*(vieL[rr]*vrj.y - vreL[rr]*vij.y));
                ni.z = fmaf(oml, hi.z, lam*(vieL[rr]*vrj.z - vreL[rr]*vij.z));
                ni.w = fmaf(oml, hi.w, lam*(vieL[rr]*vrj.w - vreL[rr]*vij.w));
            } else {
                nr.x = fmaf(oml, hr.x, xLr[rr].x);
                nr.y = fmaf(oml, hr.y, xLr[rr].y);
                nr.z = fmaf(oml, hr.z, xLr[rr].z);
                nr.w = fmaf(oml, hr.w, xLr[rr].w);
                ni.x = fmaf(oml, hi.x, xLi[rr].x);
                ni.y = fmaf(oml, hi.y, xLi[rr].y);
                ni.z = fmaf(oml, hi.z, xLi[rr].z);
                ni.w = fmaf(oml, hi.w, xLi[rr].w);
            }
            *(float4*)&sNr[e*64 + j0] = nr;
            *(float4*)&sNi[e*64 + j0] = ni;
            sq = fmaf(nr.x, nr.x, sq); sq = fmaf(nr.y, nr.y, sq);
            sq = fmaf(nr.z, nr.z, sq); sq = fmaf(nr.w, nr.w, sq);
            sq = fmaf(ni.x, ni.x, sq); sq = fmaf(ni.y, ni.y, sq);
            sq = fmaf(ni.z, ni.z, sq); sq = fmaf(ni.w, ni.w, sq);
        }

        CLUSTER_WAIT();    // peer H rows (prev step) have arrived

        // ---- N peer-half rows ----
#pragma unroll
        for (int rr = 0; rr < 2; rr++) {
            const int e = eP + rr;
            float4 hr = *(const float4*)&sHr[e*64 + j0];
            float4 hi = *(const float4*)&sHi[e*64 + j0];
            float4 nr, ni;
            if (MODE == 0) {
                nr.x = fmaf(oml, hr.x, lam*(vreP[rr]*vrj.x + vieP[rr]*vij.x));
                nr.y = fmaf(oml, hr.y, lam*(vreP[rr]*vrj.y + vieP[rr]*vij.y));
                nr.z = fmaf(oml, hr.z, lam*(vreP[rr]*vrj.z + vieP[rr]*vij.z));
                nr.w = fmaf(oml, hr.w, lam*(vreP[rr]*vrj.w + vieP[rr]*vij.w));
                ni.x = fmaf(oml, hi.x, lam*(vieP[rr]*vrj.x - vreP[rr]*vij.x));
                ni.y = fmaf(oml, hi.y, lam*(vieP[rr]*vrj.y - vreP[rr]*vij.y));
                ni.z = fmaf(oml, hi.z, lam*(vieP[rr]*vrj.z - vreP[rr]*vij.z));
                ni.w = fmaf(oml, hi.w, lam*(vieP[rr]*vrj.w - vreP[rr]*vij.w));
            } else {
                nr.x = fmaf(oml, hr.x, xPr[rr].x);
                nr.y = fmaf(oml, hr.y, xPr[rr].y);
                nr.z = fmaf(oml, hr.z, xPr[rr].z);
                nr.w = fmaf(oml, hr.w, xPr[rr].w);
                ni.x = fmaf(oml, hi.x, xPi[rr].x);
                ni.y = fmaf(oml, hi.y, xPi[rr].y);
                ni.z = fmaf(oml, hi.z, xPi[rr].z);
                ni.w = fmaf(oml, hi.w, xPi[rr].w);
            }
            *(float4*)&sNr[e*64 + j0] = nr;
            *(float4*)&sNi[e*64 + j0] = ni;
            sq = fmaf(nr.x, nr.x, sq); sq = fmaf(nr.y, nr.y, sq);
            sq = fmaf(nr.z, nr.z, sq); sq = fmaf(nr.w, nr.w, sq);
            sq = fmaf(ni.x, ni.x, sq); sq = fmaf(ni.y, ni.y, sq);
            sq = fmaf(ni.z, ni.z, sq); sq = fmaf(ni.w, ni.w, sq);
        }
        // deterministic reduce: warp tree -> red[8] -> fixed-order sum
#pragma unroll
        for (int o = 16; o > 0; o >>= 1)
            sq += __shfl_down_sync(0xffffffffu, sq, o);
        if ((tid & 31) == 0) red[tid >> 5] = sq;
        __syncthreads();   // sN + red visible
        const float tr = ((((((red[0]+red[1])+red[2])+red[3])+red[4])+red[5])+red[6])+red[7];

        // ---- C[myrows,:] = N[myrows,:] @ N (complex square), grouped b-loads ----
        UF cR[2], cI[2];
#pragma unroll
        for (int r = 0; r < 2; r++) { cR[r].f = make_float4(0,0,0,0); cI[r].f = make_float4(0,0,0,0); }
#pragma unroll 2
        for (int k0 = 0; k0 < 64; k0 += 4) {
            UF br[4], bi[4];
#pragma unroll
            for (int kk = 0; kk < 4; kk++) {
                br[kk].f = *(const float4*)&sNr[(k0+kk)*64 + j0];
                bi[kk].f = *(const float4*)&sNi[(k0+kk)*64 + j0];
            }
            float4 ar4[2], ai4[2];
#pragma unroll
            for (int r = 0; r < 2; r++) {
                ar4[r] = *(const float4*)&sNr[(g0+r)*64 + k0];
                ai4[r] = *(const float4*)&sNi[(g0+r)*64 + k0];
            }
#pragma unroll
            for (int kk = 0; kk < 4; kk++) {
#pragma unroll
                for (int r = 0; r < 2; r++) {
                    float av  = GETC(ar4[r], kk);
                    float avi = GETC(ai4[r], kk);
                    u64 arp = pk2(av);
                    u64 aip = pk2(avi);
                    u64 ain = pk2(-avi);
                    fma2(cR[r].u.x, arp, br[kk].u.x); fma2(cR[r].u.y, arp, br[kk].u.y);
                    fma2(cR[r].u.x, ain, bi[kk].u.x); fma2(cR[r].u.y, ain, bi[kk].u.y);
                    fma2(cI[r].u.x, arp, bi[kk].u.x); fma2(cI[r].u.y, arp, bi[kk].u.y);
                    fma2(cI[r].u.x, aip, br[kk].u.x); fma2(cI[r].u.y, aip, br[kk].u.y);
                }
            }
        }

        // ---- epilogue: H' = b*C/tr + (1-b)*N ; local + peer + gmem ----
        const float sc = BETAC / tr;
        float* gr = g_L1r + ((size_t)t*NB + b)*4096;
        float* gi = g_L1i + ((size_t)t*NB + b)*4096;
#pragma unroll
        for (int rr = 0; rr < 2; rr++) {
            const int g = g0 + rr;
            float4 nr = *(const float4*)&sNr[g*64 + j0];
            float4 ni = *(const float4*)&sNi[g*64 + j0];
            float4 hR, hI;
            hR.x = fmaf(sc, cR[rr].f.x, ob*nr.x);  hR.y = fmaf(sc, cR[rr].f.y, ob*nr.y);
            hR.z = fmaf(sc, cR[rr].f.z, ob*nr.z);  hR.w = fmaf(sc, cR[rr].f.w, ob*nr.w);
            hI.x = fmaf(sc, cI[rr].f.x, ob*ni.x);  hI.y = fmaf(sc, cI[rr].f.y, ob*ni.y);
            hI.z = fmaf(sc, cI[rr].f.z, ob*ni.z);  hI.w = fmaf(sc, cI[rr].f.w, ob*ni.w);
            *(float4*)&dHr[g*64 + j0] = hR;
            *(float4*)&dHi[g*64 + j0] = hI;
            stsc16(pdHr + (uint32_t)(g*64 + j0)*4u, hR);
            stsc16(pdHi + (uint32_t)(g*64 + j0)*4u, hI);
            *(float4*)&gr[g*64 + j0] = hR;
            *(float4*)&gi[g*64 + j0] = hI;
        }
        __syncthreads();   // local H writes visible CTA-wide
        CLUSTER_ARRIVE();  // release H stores to peer
    }

    CLUSTER_WAIT();
    CLUSTER_SYNC();        // no exit while peer DSMEM stores in flight
}

// ---------------- K3: layer-2 x-side conjugation (tilde frame, A_t) --------
__global__ void __launch_bounds__(256) uxconj_kernel(const float* __restrict__ lam_ptr)
{
    extern __shared__ float sm[];
    float* sUx  = sm;
    float* sUxT = sm + 4096;
    float* sXr  = sm + 8192;
    float* sXi  = sm + 12288;
    float* sTr  = sm + 16384;
    float* sTi  = sm + 20480;
    const int tid = threadIdx.x;
    const int tx = tid & 15, ty = tid >> 4;
    const int i0 = ty * 4;
    const float lam = sigmoidf_(lam_ptr[0]);
    const size_t base = (size_t)blockIdx.x * 4096;
    const float* At = g_A + (size_t)(blockIdx.x >> 6) * 4096;   // blk = t*NB+b

    for (int i = tid; i < ND*ND; i += 256) {
        float v = At[i];
        sUx[i] = v;
        sUxT[(i & 63)*64 + (i >> 6)] = v;
        sXr[i] = g_L1r[base + i];
        sXi[i] = g_L1i[base + i];
    }
    __syncthreads();

    {
        UF aR[4], aI[4];
#pragma unroll
        for (int r = 0; r < 4; r++) { aR[r].f = make_float4(0,0,0,0); aI[r].f = make_float4(0,0,0,0); }
        const ulonglong2* xr2 = (const ulonglong2*)sXr;
        const ulonglong2* xi2 = (const ulonglong2*)sXi;
#pragma unroll 2
        for (int k0 = 0; k0 < ND; k0 += 4) {
            ulonglong2 br[4], bi[4];
#pragma unroll
            for (int kk = 0; kk < 4; kk++) {
                br[kk] = xr2[(k0+kk)*16 + tx];
                bi[kk] = xi2[(k0+kk)*16 + tx];
            }
            float4 a4[4];
#pragma unroll
            for (int r = 0; r < 4; r++) a4[r] = *(const float4*)&sUx[(i0+r)*64 + k0];
#pragma unroll
            for (int kk = 0; kk < 4; kk++) {
#pragma unroll
                for (int r = 0; r < 4; r++) {
                    u64 ap = pk2(GETC(a4[r], kk));
                    fma2(aR[r].u.x, ap, br[kk].x); fma2(aR[r].u.y, ap, br[kk].y);
                    fma2(aI[r].u.x, ap, bi[kk].x); fma2(aI[r].u.y, ap, bi[kk].y);
                }
            }
        }
#pragma unroll
        for (int r = 0; r < 4; r++) {
            ((float4*)sTr)[(i0+r)*16 + tx] = aR[r].f;
            ((float4*)sTi)[(i0+r)*16 + tx] = aI[r].f;
        }
    }
    __syncthreads();

    {
        UF oR[4], oI[4];
#pragma unroll
        for (int r = 0; r < 4; r++) { oR[r].f = make_float4(0,0,0,0); oI[r].f = make_float4(0,0,0,0); }
        const ulonglong2* uxT2 = (const ulonglong2*)sUxT;
#pragma unroll 2
        for (int k0 = 0; k0 < ND; k0 += 4) {
            ulonglong2 b4[4];
#pragma unroll
            for (int kk = 0; kk < 4; kk++) b4[kk] = uxT2[(k0+kk)*16 + tx];
            float4 ar4[4], ai4[4];
#pragma unroll
            for (int r = 0; r < 4; r++) {
                ar4[r] = *(const float4*)&sTr[(i0+r)*64 + k0];
                ai4[r] = *(const float4*)&sTi[(i0+r)*64 + k0];
            }
#pragma unroll
            for (int kk = 0; kk < 4; kk++) {
#pragma unroll
                for (int r = 0; r < 4; r++) {
                    u64 arp = pk2(GETC(ar4[r], kk));
                    u64 aip = pk2(GETC(ai4[r], kk));
                    fma2(oR[r].u.x, arp, b4[kk].x); fma2(oR[r].u.y, arp, b4[kk].y);
                    fma2(oI[r].u.x, aip, b4[kk].x); fma2(oI[r].u.y, aip, b4[kk].y);
                }
            }
        }
        float4* gr = (float4*)(g_ux2r + base);
        float4* gi = (float4*)(g_ux2i + base);
#pragma unroll
        for (int r = 0; r < 4; r++) {
            float4 vR = oR[r].f, vI = oI[r].f;
            vR.x *= lam; vR.y *= lam; vR.z *= lam; vR.w *= lam;
            vI.x *= lam; vI.y *= lam; vI.z *= lam; vI.w *= lam;
            gr[(i0+r)*16 + tx] = vR;
            gi[(i0+r)*16 + tx] = vI;
        }
    }
}

// ---------------- K5: dense + measurement + log (tilde frame, P_t) ---------
__global__ void __launch_bounds__(256) dense_meas_kernel(const float* __restrict__ dlam_ptr,
                                                         const float* __restrict__ mk,
                                                         float* __restrict__ out)
{
    __shared__ float sRr[ND*ND], sRi[ND*ND];
    __shared__ float sW[ND*NC];
    __shared__ float tmpr[ND*NC], tmpi[ND*NC];
    __shared__ float sgr[NC*NC], sgi[NC*NC];
    __shared__ float svr[NC*NC], svi[NC*NC];
    const int blk = blockIdx.x;     // t*NB + b
    const int tid = threadIdx.x;
    const size_t base = (size_t)blk * 4096;
    const float* Pt = g_P + (size_t)(blk >> 6) * 640;

    for (int i = tid; i < ND*ND; i += 256) { sRr[i] = g_L1r[base + i]; sRi[i] = g_L1i[base + i]; }
    for (int i = tid; i < ND*NC; i += 256) sW[i] = Pt[i];
    if (tid < NC) {
        float nrm = 0.f;
        for (int c = 0; c < NC; c++) {
            float vr = mk[(tid*NC + c)*2 + 0];
            float vi = mk[(tid*NC + c)*2 + 1];
            nrm += vr*vr + vi*vi;
        }
        float inv = 1.0f / sqrtf(nrm);
        for (int c = 0; c < NC; c++) {
            svr[tid*NC + c] = mk[(tid*NC + c)*2 + 0] * inv;
            svi[tid*NC + c] = mk[(tid*NC + c)*2 + 1] * inv;
        }
    }
    __syncthreads();

    for (int idx = tid; idx < ND*NC; idx += 256) {
        int d = idx / NC, c = idx % NC;
        float ar = 0.f, ai = 0.f;
#pragma unroll 4
        for (int e = 0; e < ND; e++) {
            float w = sW[e*NC + c];
            ar = fmaf(sRr[d*64 + e], w, ar);
            ai = fmaf(sRi[d*64 + e], w, ai);
        }
        tmpr[idx] = ar; tmpi[idx] = ai;
    }
    __syncthreads();

    if (tid < NC*NC) {
        int c = tid / NC, f = tid % NC;
        float ar = 0.f, ai = 0.f;
#pragma unroll 4
        for (int d = 0; d < ND; d++) {
            float w = sW[d*NC + c];
            ar = fmaf(w, tmpr[d*NC + f], ar);
            ai = fmaf(w, tmpi[d*NC + f], ai);
        }
        float dlam = sigmoidf_(dlam_ptr[0]);
        ar = dlam * ar + ((c == f) ? (1.0f - dlam) / NC : 0.0f);
        ai = dlam * ai;
        sgr[tid] = ar; sgi[tid] = ai;
    }
    __syncthreads();

    if (tid < NC) {
        float tr = 0.f;
        for (int c = 0; c < NC; c++) tr += sgr[c*NC + c];
        float invtr = 1.0f / tr;
        int k = tid;
        float p = 0.f;
        for (int c = 0; c < NC; c++) {
            float vrc = svr[k*NC + c], vic = svi[k*NC + c];
            for (int d = 0; d < NC; d++) {
                float vrd = svr[k*NC + d], vid = svi[k*NC + d];
                p += (vrc*vrd + vic*vid) * sgr[c*NC + d]
                   + (vic*vrd - vrc*vid) * sgi[c*NC + d];
            }
        }
        p *= invtr;
        int t = blk / NB, b = blk % NB;
        out[((size_t)b*NT + t)*NC + k] = logf(p);
    }
}

// ---------------- launch ----------------
extern "C" void kernel_launch(void* const* d_in, const int* in_sizes, int n_in,
                              void* d_out, int out_size)
{
    const float* x        = (const float*)d_in[0];
    const float* amp_w    = (const float*)d_in[1];
    const float* amp_b    = (const float*)d_in[2];
    const float* phase_w  = (const float*)d_in[3];
    const float* phase_b  = (const float*)d_in[4];
    const float* Ux       = (const float*)d_in[5];
    const float* Uh       = (const float*)d_in[6];
    const float* cell_l   = (const float*)d_in[7];
    const float* dense_w  = (const float*)d_in[8];
    const float* dense_l  = (const float*)d_in[9];
    const float* meas     = (const float*)d_in[10];
    float* out = (float*)d_out;

    const int SCAN_SMEM = SCAN2_FLOATS * 4;      // 96 KB
    const int UX_SMEM   = 6 * 4096 * 4;          // 96 KB
    const int MAPS_SMEM = (3*4096 + 640) * 4;    // ~51.7 KB
    cudaFuncSetAttribute(scan2_kernel<0>, cudaFuncAttributeMaxDynamicSharedMemorySize, SCAN_SMEM);
    cudaFuncSetAttribute(scan2_kernel<1>, cudaFuncAttributeMaxDynamicSharedMemorySize, SCAN_SMEM);
    cudaFuncSetAttribute(uxconj_kernel,   cudaFuncAttributeMaxDynamicSharedMemorySize, UX_SMEM);
    cudaFuncSetAttribute(maps_kernel,     cudaFuncAttributeMaxDynamicSharedMemorySize, MAPS_SMEM);

    // precompute all W powers in one launch (log-depth via ready flags)
    zero_flags<<<1, 256>>>();
    powers_kernel<<<NT, 256>>>(Uh);
    maps_kernel<<<NT, 256, MAPS_SMEM>>>(Ux, dense_w);

    proj_kernel<<<NB*NT, ND>>>(x, amp_w, amp_b, phase_w, phase_b);
    scan2_kernel<0><<<NB*2, 256, SCAN_SMEM>>>(cell_l);
    uxconj_kernel<<<NT*NB, 256, UX_SMEM>>>(cell_l);
    scan2_kernel<1><<<NB*2, 256, SCAN_SMEM>>>(cell_l);
    dense_meas_kernel<<<NT*NB, 256>>>(dense_l, meas, out);
}